// round 2
// baseline (speedup 1.0000x reference)
#include <cuda_runtime.h>
#include <cuda_fp16.h>
#include <mma.h>
#include <cstdint>

using namespace nvcuda;

// ============================================================
// Problem dims (fixed per reference)
// ============================================================
#define M_TOTAL 16384   // B*S
#define N_TOTAL 4096    // D_OUT
#define K_TOTAL 4096    // D_IN

// CTA tile
#define BM 128
#define BN 256
#define BK 64
#define STAGES 3
#define KITERS (K_TOTAL / BK)     // 64
#define GRID_N (N_TOTAL / BN)     // 16
#define GRID_M (M_TOTAL / BM)     // 128

#define NTHREADS 256              // 8 warps: 2 (M) x 4 (N), warp tile 64x64

// Smem layout: padded rows to kill LDSM bank conflicts.
// 64 halves data + 8 halves pad = 72 halves = 144B row stride.
#define PAD_LD 72
#define A_STAGE_BYTES (BM * PAD_LD * 2)          // 18432
#define B_STAGE_BYTES (BN * PAD_LD * 2)          // 36864
#define STAGE_BYTES   (A_STAGE_BYTES + B_STAGE_BYTES)   // 55296
#define SMEM_BIAS_BYTES 1024
#define SMEM_TOTAL (SMEM_BIAS_BYTES + STAGES * STAGE_BYTES)  // 166912
#define EPI_PITCH 260   // floats; 1040B rows -> 16B aligned, 4-bank row shift

// fp16 scratch (static device globals: no runtime allocation)
__device__ __align__(1024) __half g_xh[(size_t)M_TOTAL * K_TOTAL];
__device__ __align__(1024) __half g_wh[(size_t)N_TOTAL * K_TOTAL];

// ============================================================
// cp.async helpers (sm_80 base ISA — safe under compute_103)
// ============================================================
__device__ __forceinline__ uint32_t smem_to_u32(const void* p) {
    uint32_t a;
    asm("{ .reg .u64 t; cvta.to.shared.u64 t, %1; cvt.u32.u64 %0, t; }" : "=r"(a) : "l"(p));
    return a;
}

__device__ __forceinline__ void cp_async16(uint32_t saddr, const void* gptr) {
    asm volatile("cp.async.cg.shared.global [%0], [%1], 16;" :: "r"(saddr), "l"(gptr));
}

__device__ __forceinline__ void cp_commit() {
    asm volatile("cp.async.commit_group;");
}

template <int N>
__device__ __forceinline__ void cp_wait_group() {
    asm volatile("cp.async.wait_group %0;" :: "n"(N));
}

// ============================================================
// fp32 -> fp16 conversion
// ============================================================
__global__ void f32_to_f16_kernel(const float4* __restrict__ src, uint2* __restrict__ dst, int n4) {
    int i = blockIdx.x * blockDim.x + threadIdx.x;
    if (i < n4) {
        float4 v = src[i];
        __half2 a = __floats2half2_rn(v.x, v.y);
        __half2 b = __floats2half2_rn(v.z, v.w);
        uint2 o;
        o.x = *reinterpret_cast<uint32_t*>(&a);
        o.y = *reinterpret_cast<uint32_t*>(&b);
        dst[i] = o;
    }
}

// ============================================================
// GEMM: out[M,N] = x[M,K] @ W[N,K]^T + bias
// 3-stage cp.async pipeline, wmma (HMMA) fp16 -> fp32 accumulate
// ============================================================
__global__ void __launch_bounds__(NTHREADS, 1) gemm_f16_kernel(
    const __half* __restrict__ xh,
    const __half* __restrict__ wh,
    const float* __restrict__ bias,
    float* __restrict__ out)
{
    extern __shared__ char smem[];
    const uint32_t smem_u32 = smem_to_u32(smem);
    const int tid = threadIdx.x;
    const int wid = tid >> 5;
    const int wm = wid >> 2;       // 0..1  (M warp)
    const int wn = wid & 3;        // 0..3  (N warp)

    const int tile_n = (int)(blockIdx.x % GRID_N);
    const int tile_m = (int)(blockIdx.x / GRID_N);
    const int m0 = tile_m * BM;
    const int n0 = tile_n * BN;

    // Stage bias tile into smem
    float* sbias = reinterpret_cast<float*>(smem);
    for (int i = tid; i < BN; i += NTHREADS) sbias[i] = bias[n0 + i];

    // Copy-issue for one K stage into pipeline buffer `stage`
    const __half* gA_base = xh + (size_t)m0 * K_TOTAL;
    const __half* gW_base = wh + (size_t)n0 * K_TOTAL;

    auto issue_copy = [&](int kt, int stage) {
        const uint32_t sa = smem_u32 + SMEM_BIAS_BYTES + (uint32_t)stage * STAGE_BYTES;
        const uint32_t sb = sa + A_STAGE_BYTES;
        const __half* gA = gA_base + kt * BK;
        const __half* gW = gW_base + kt * BK;
        // A: 128 rows x 8 chunks(16B) = 1024 chunks
        #pragma unroll
        for (int i = 0; i < 4; i++) {
            int idx = tid + i * NTHREADS;
            int r = idx >> 3, c = idx & 7;
            cp_async16(sa + (uint32_t)r * (PAD_LD * 2) + (uint32_t)c * 16,
                       gA + (size_t)r * K_TOTAL + c * 8);
        }
        // B: 256 rows x 8 chunks = 2048 chunks
        #pragma unroll
        for (int i = 0; i < 8; i++) {
            int idx = tid + i * NTHREADS;
            int r = idx >> 3, c = idx & 7;
            cp_async16(sb + (uint32_t)r * (PAD_LD * 2) + (uint32_t)c * 16,
                       gW + (size_t)r * K_TOTAL + c * 8);
        }
    };

    // Accumulators: 4x4 wmma tiles of 16x16 (warp tile 64x64)
    wmma::fragment<wmma::accumulator, 16, 16, 16, float> acc[4][4];
    #pragma unroll
    for (int mi = 0; mi < 4; mi++)
        #pragma unroll
        for (int ni = 0; ni < 4; ni++)
            wmma::fill_fragment(acc[mi][ni], 0.0f);

    // Pipeline prologue
    #pragma unroll
    for (int s = 0; s < STAGES - 1; s++) {
        issue_copy(s, s);
        cp_commit();
    }

    // Main loop
    for (int kt = 0; kt < KITERS; kt++) {
        cp_wait_group<STAGES - 2>();
        __syncthreads();

        // Prefetch next tile (into the buffer consumed STAGES-1 iters ago)
        int knext = kt + STAGES - 1;
        if (knext < KITERS) issue_copy(knext, knext % STAGES);
        cp_commit();   // commit even if empty: keeps group counting consistent

        const int stage = kt % STAGES;
        const __half* sA = reinterpret_cast<const __half*>(
            smem + SMEM_BIAS_BYTES + (size_t)stage * STAGE_BYTES);
        const __half* sB = reinterpret_cast<const __half*>(
            smem + SMEM_BIAS_BYTES + (size_t)stage * STAGE_BYTES + A_STAGE_BYTES);

        #pragma unroll
        for (int ks = 0; ks < BK / 16; ks++) {
            wmma::fragment<wmma::matrix_a, 16, 16, 16, __half, wmma::row_major> af[4];
            #pragma unroll
            for (int mi = 0; mi < 4; mi++)
                wmma::load_matrix_sync(af[mi],
                    sA + (size_t)(wm * 64 + mi * 16) * PAD_LD + ks * 16, PAD_LD);
            #pragma unroll
            for (int ni = 0; ni < 4; ni++) {
                wmma::fragment<wmma::matrix_b, 16, 16, 16, __half, wmma::col_major> bf;
                wmma::load_matrix_sync(bf,
                    sB + (size_t)(wn * 64 + ni * 16) * PAD_LD + ks * 16, PAD_LD);
                #pragma unroll
                for (int mi = 0; mi < 4; mi++)
                    wmma::mma_sync(acc[mi][ni], af[mi], bf, acc[mi][ni]);
            }
        }
        __syncthreads();
    }

    // ---- Epilogue: frags -> smem staging (reuse pipeline buffers) -> +bias -> gmem
    float* staging = reinterpret_cast<float*>(smem + SMEM_BIAS_BYTES);
    #pragma unroll
    for (int mi = 0; mi < 4; mi++)
        #pragma unroll
        for (int ni = 0; ni < 4; ni++)
            wmma::store_matrix_sync(
                staging + (size_t)(wm * 64 + mi * 16) * EPI_PITCH + wn * 64 + ni * 16,
                acc[mi][ni], EPI_PITCH, wmma::mem_row_major);
    __syncthreads();

    // Coalesced write-out: 128 rows x 64 float4
    #pragma unroll 4
    for (int idx = tid; idx < BM * (BN / 4); idx += NTHREADS) {
        int rr = idx >> 6;
        int c4 = idx & 63;
        float4 v = *reinterpret_cast<const float4*>(staging + (size_t)rr * EPI_PITCH + c4 * 4);
        v.x += sbias[c4 * 4 + 0];
        v.y += sbias[c4 * 4 + 1];
        v.z += sbias[c4 * 4 + 2];
        v.w += sbias[c4 * 4 + 3];
        *reinterpret_cast<float4*>(out + (size_t)(m0 + rr) * N_TOTAL + n0 + c4 * 4) = v;
    }
}

// ============================================================
// Host launcher
// ============================================================
extern "C" void kernel_launch(void* const* d_in, const int* in_sizes, int n_in,
                              void* d_out, int out_size) {
    const float* x    = (const float*)d_in[0];   // [16384, 4096]
    const float* w    = (const float*)d_in[1];   // [4096, 4096]
    const float* bias = (const float*)d_in[2];   // [4096]
    float* out = (float*)d_out;

    __half* xh = nullptr;
    __half* wh = nullptr;
    cudaGetSymbolAddress((void**)&xh, g_xh);
    cudaGetSymbolAddress((void**)&wh, g_wh);

    // fp32 -> fp16 conversion
    {
        int n4x = (M_TOTAL * (size_t)K_TOTAL) / 4;
        int n4w = (N_TOTAL * (size_t)K_TOTAL) / 4;
        f32_to_f16_kernel<<<(n4x + 255) / 256, 256>>>((const float4*)x, (uint2*)xh, n4x);
        f32_to_f16_kernel<<<(n4w + 255) / 256, 256>>>((const float4*)w, (uint2*)wh, n4w);
    }

    static bool attr_set = false;
    if (!attr_set) {
        cudaFuncSetAttribute(gemm_f16_kernel, cudaFuncAttributeMaxDynamicSharedMemorySize,
                             SMEM_TOTAL);
        attr_set = true;
    }
    gemm_f16_kernel<<<GRID_M * GRID_N, NTHREADS, SMEM_TOTAL>>>(xh, wh, bias, out);
}